// round 14
// baseline (speedup 1.0000x reference)
#include <cuda_runtime.h>
#include <math.h>

typedef unsigned long long u64;

#define B_ 4
#define S_ 2048
#define C_ 128
#define H_ 8
#define D_ 16
#define BH_ (B_*H_)
#define SPLITS 8
#define JSPLIT (S_/SPLITS)   // 256 keys per split (staged whole)
#define QT2 256              // q rows per attn CTA (2 per thread)

#define LOG2E 1.4426950408889634f
#define EXP_OFF2 5.7707801636f   // 4.0 * log2(e), applied in log2 domain

// Scratch (device globals: no allocs allowed).
__device__ float g_q[(size_t)BH_*S_*D_];
__device__ float g_k[(size_t)BH_*S_*D_];
__device__ float g_v[(size_t)BH_*S_*D_];
// split-K partials: per (bh, row, split): l, o[16] (unnormalized, shared offset)
__device__ float g_pl[(size_t)BH_*S_*SPLITS];
__device__ float g_po[(size_t)BH_*S_*SPLITS*D_];

// ---- packed f32x2 helpers (FFMA2: PTX-only, 2x fp32 FMA throughput) ----
__device__ __forceinline__ u64 pk2(float lo, float hi) {
    u64 r; asm("mov.b64 %0,{%1,%2};" : "=l"(r) : "f"(lo), "f"(hi)); return r;
}
__device__ __forceinline__ void upk2(u64 v, float& lo, float& hi) {
    asm("mov.b64 {%0,%1},%2;" : "=f"(lo), "=f"(hi) : "l"(v));
}
__device__ __forceinline__ u64 fma2_(u64 a, u64 b, u64 c) {
    u64 d; asm("fma.rn.f32x2 %0,%1,%2,%3;" : "=l"(d) : "l"(a), "l"(b), "l"(c)); return d;
}
__device__ __forceinline__ u64 mul2_(u64 a, u64 b) {
    u64 d; asm("mul.rn.f32x2 %0,%1,%2;" : "=l"(d) : "l"(a), "l"(b)); return d;
}
__device__ __forceinline__ u64 add2_(u64 a, u64 b) {
    u64 d; asm("add.rn.f32x2 %0,%1,%2;" : "=l"(d) : "l"(a), "l"(b)); return d;
}
__device__ __forceinline__ float ex2_(float x) {
    float y; asm("ex2.approx.f32 %0,%1;" : "=f"(y) : "f"(x)); return y;
}
// 16-byte shared load -> two u64 pairs (LDS.128), immediate offset folded in.
#define LDSV2(a, b, addr, OFF) \
    asm volatile("ld.shared.v2.b64 {%0,%1},[%2+" #OFF "];" \
                 : "=l"(a), "=l"(b) : "r"(addr))

// ============================================================================
// Projection: out[b,h,s,d] = sum_c x[b,s,c] * w[h*16+d, c]  (q scaled 1/4)
// 256 threads, 8 rows x 4 cols per thread (high ILP).
// ============================================================================
#define PR 64     // x rows per CTA
#define WS 132    // padded stride for w_s
#define XS 68     // padded stride for x_sT

__global__ __launch_bounds__(256) void proj_kernel(
    const float* __restrict__ q_x, const float* __restrict__ kv_x,
    const float* __restrict__ w_q, const float* __restrict__ w_k,
    const float* __restrict__ w_v)
{
    extern __shared__ float sm[];
    float* w_s = sm;               // w_s[c*WS + o]
    float* x_s = sm + C_ * WS;     // x_s[c*XS + r]

    int proj = blockIdx.y;
    const float* x  = (proj == 0) ? q_x : kv_x;
    const float* w  = (proj == 0) ? w_q : (proj == 1 ? w_k : w_v);
    float*       og = (proj == 0) ? g_q : (proj == 1 ? g_k : g_v);
    float scale = (proj == 0) ? 0.25f : 1.0f;   // 1/sqrt(16)

    int tid  = threadIdx.x;
    int row0 = blockIdx.x * PR;

    for (int i = tid; i < C_ * C_; i += 256) {
        int o = i >> 7, c = i & 127;
        w_s[c * WS + o] = w[i];
    }
    {
        const float* xg = x + (size_t)row0 * C_;
        for (int i = tid; i < PR * C_; i += 256) {
            int r = i >> 7, c = i & 127;
            x_s[c * XS + r] = xg[i];
        }
    }
    __syncthreads();

    int rg = tid >> 5, cg = tid & 31;
    int r0 = rg * 8, c0 = cg * 4;

    unsigned wb = (unsigned)__cvta_generic_to_shared(w_s) + c0 * 4;
    unsigned xb = (unsigned)__cvta_generic_to_shared(x_s) + r0 * 4;

    u64 acc[4][4];
#pragma unroll
    for (int m = 0; m < 4; m++)
#pragma unroll
        for (int j = 0; j < 4; j++) acc[m][j] = 0ull;

#pragma unroll 8
    for (int k = 0; k < C_; k++) {
        u64 b01, b23;
        LDSV2(b01, b23, wb + k * (WS * 4), 0);
        u64 x01, x23, x45, x67;
        unsigned xa = xb + k * (XS * 4);
        LDSV2(x01, x23, xa, 0);
        LDSV2(x45, x67, xa, 16);

        float b0, b1, b2, b3;
        upk2(b01, b0, b1); upk2(b23, b2, b3);
        u64 bd0 = pk2(b0, b0), bd1 = pk2(b1, b1);
        u64 bd2 = pk2(b2, b2), bd3 = pk2(b3, b3);

        acc[0][0] = fma2_(x01, bd0, acc[0][0]);
        acc[0][1] = fma2_(x01, bd1, acc[0][1]);
        acc[0][2] = fma2_(x01, bd2, acc[0][2]);
        acc[0][3] = fma2_(x01, bd3, acc[0][3]);
        acc[1][0] = fma2_(x23, bd0, acc[1][0]);
        acc[1][1] = fma2_(x23, bd1, acc[1][1]);
        acc[1][2] = fma2_(x23, bd2, acc[1][2]);
        acc[1][3] = fma2_(x23, bd3, acc[1][3]);
        acc[2][0] = fma2_(x45, bd0, acc[2][0]);
        acc[2][1] = fma2_(x45, bd1, acc[2][1]);
        acc[2][2] = fma2_(x45, bd2, acc[2][2]);
        acc[2][3] = fma2_(x45, bd3, acc[2][3]);
        acc[3][0] = fma2_(x67, bd0, acc[3][0]);
        acc[3][1] = fma2_(x67, bd1, acc[3][1]);
        acc[3][2] = fma2_(x67, bd2, acc[3][2]);
        acc[3][3] = fma2_(x67, bd3, acc[3][3]);
    }

    int h  = c0 >> 4;
    int d0 = c0 & 15;
#pragma unroll
    for (int m = 0; m < 4; m++) {
        float lo[4], hi[4];
#pragma unroll
        for (int j = 0; j < 4; j++) upk2(acc[m][j], lo[j], hi[j]);
        int gr = row0 + r0 + 2 * m;
        int b  = gr >> 11;
        int s  = gr & 2047;
        float* base = &og[((size_t)(b * H_ + h) * S_ + s) * D_ + d0];
        *(float4*)base = make_float4(lo[0] * scale, lo[1] * scale,
                                     lo[2] * scale, lo[3] * scale);
        *(float4*)(base + D_) = make_float4(hi[0] * scale, hi[1] * scale,
                                            hi[2] * scale, hi[3] * scale);
    }
}

// ============================================================================
// Attention (split-K x8, 2 q-rows/thread, key-pair packed scores):
// __launch_bounds__(128, 3): reg budget 170 -> NO SPILLS (this is the round's
// single change vs R11's (128,4) whose 128-reg cap spilled).
// Grid 2048 CTAs over 444 slots = 4.61 waves -> 92% wave efficiency.
// ============================================================================
__global__ __launch_bounds__(128, 3) void attn_kernel()
{
    extern __shared__ float smv[];
    float*  kt  = smv;                           // 16 KB (transposed key pairs)
    float4* v_s = (float4*)(smv + JSPLIT * D_);  // 16 KB

    int split = blockIdx.x & (SPLITS - 1);
    int qb    = blockIdx.x >> 3;
    int b = blockIdx.z, h = blockIdx.y;
    int bh = b * H_ + h;
    int rowA = qb * QT2 + threadIdx.x;
    int rowB = rowA + 128;

    // q rows as BROADCAST pairs, pre-scaled by log2(e)
    u64 qa2[16], qb2[16];
    {
        const float* ga = g_q + ((size_t)bh * S_ + rowA) * D_;
        const float* gb = g_q + ((size_t)bh * S_ + rowB) * D_;
#pragma unroll
        for (int i = 0; i < 4; i++) {
            float4 t = ((const float4*)ga)[i];
            float4 u = ((const float4*)gb)[i];
            qa2[4*i+0] = pk2(t.x * LOG2E, t.x * LOG2E);
            qa2[4*i+1] = pk2(t.y * LOG2E, t.y * LOG2E);
            qa2[4*i+2] = pk2(t.z * LOG2E, t.z * LOG2E);
            qa2[4*i+3] = pk2(t.w * LOG2E, t.w * LOG2E);
            qb2[4*i+0] = pk2(u.x * LOG2E, u.x * LOG2E);
            qb2[4*i+1] = pk2(u.y * LOG2E, u.y * LOG2E);
            qb2[4*i+2] = pk2(u.z * LOG2E, u.z * LOG2E);
            qb2[4*i+3] = pk2(u.w * LOG2E, u.w * LOG2E);
        }
    }

    u64 oa[8], ob[8];
#pragma unroll
    for (int i = 0; i < 8; i++) { oa[i] = 0ull; ob[i] = 0ull; }
    u64 la2 = 0ull, lb2 = 0ull;   // packed (key0, key1) row-sum accumulators

    int j0 = split * JSPLIT;
    // stage K transposed + V linear
    {
        const float4* kg = (const float4*)(g_k + ((size_t)bh * S_ + j0) * D_);
        for (int i = threadIdx.x; i < JSPLIT * 4; i += 128) {
            int j = i >> 2, dc = i & 3;
            float4 t = kg[i];
            float* dst = &kt[(j >> 1) * 32 + dc * 8 + (j & 1)];
            dst[0] = t.x; dst[2] = t.y; dst[4] = t.z; dst[6] = t.w;
        }
        const float4* vg = (const float4*)(g_v + ((size_t)bh * S_ + j0) * D_);
        for (int i = threadIdx.x; i < JSPLIT * 4; i += 128)
            v_s[i] = vg[i];
    }
    __syncthreads();

    unsigned ksb = (unsigned)__cvta_generic_to_shared(kt);
    unsigned vsb = (unsigned)__cvta_generic_to_shared(v_s);
    u64 noff2 = pk2(-EXP_OFF2, -EXP_OFF2);

#pragma unroll 2
    for (int jp = 0; jp < JSPLIT / 2; jp++) {
        unsigned ka = ksb + jp * 128;
        u64 t0,t1,t2,t3,t4,t5,t6,t7,t8,t9,t10,t11,t12,t13,t14,t15;
        LDSV2(t0, t1, ka, 0);
        LDSV2(t2, t3, ka, 16);
        LDSV2(t4, t5, ka, 32);
        LDSV2(t6, t7, ka, 48);
        LDSV2(t8, t9, ka, 64);
        LDSV2(t10, t11, ka, 80);
        LDSV2(t12, t13, ka, 96);
        LDSV2(t14, t15, ka, 112);

        // row A: two partial chains, offset folded into seed
        u64 sA0 = fma2_(qa2[0], t0, noff2);
        u64 sA1 = mul2_(qa2[8], t8);
        sA0 = fma2_(qa2[1], t1, sA0);   sA1 = fma2_(qa2[9],  t9,  sA1);
        sA0 = fma2_(qa2[2], t2, sA0);   sA1 = fma2_(qa2[10], t10, sA1);
        sA0 = fma2_(qa2[3], t3, sA0);   sA1 = fma2_(qa2[11], t11, sA1);
        sA0 = fma2_(qa2[4], t4, sA0);   sA1 = fma2_(qa2[12], t12, sA1);
        sA0 = fma2_(qa2[5], t5, sA0);   sA1 = fma2_(qa2[13], t13, sA1);
        sA0 = fma2_(qa2[6], t6, sA0);   sA1 = fma2_(qa2[14], t14, sA1);
        sA0 = fma2_(qa2[7], t7, sA0);   sA1 = fma2_(qa2[15], t15, sA1);
        sA0 = add2_(sA0, sA1);

        // row B
        u64 sB0 = fma2_(qb2[0], t0, noff2);
        u64 sB1 = mul2_(qb2[8], t8);
        sB0 = fma2_(qb2[1], t1, sB0);   sB1 = fma2_(qb2[9],  t9,  sB1);
        sB0 = fma2_(qb2[2], t2, sB0);   sB1 = fma2_(qb2[10], t10, sB1);
        sB0 = fma2_(qb2[3], t3, sB0);   sB1 = fma2_(qb2[11], t11, sB1);
        sB0 = fma2_(qb2[4], t4, sB0);   sB1 = fma2_(qb2[12], t12, sB1);
        sB0 = fma2_(qb2[5], t5, sB0);   sB1 = fma2_(qb2[13], t13, sB1);
        sB0 = fma2_(qb2[6], t6, sB0);   sB1 = fma2_(qb2[14], t14, sB1);
        sB0 = fma2_(qb2[7], t7, sB0);   sB1 = fma2_(qb2[15], t15, sB1);
        sB0 = add2_(sB0, sB1);

        float sa0, sa1, sb0, sb1;
        upk2(sA0, sa0, sa1);
        upk2(sB0, sb0, sb1);
        float pa0 = ex2_(sa0), pa1 = ex2_(sa1);
        float pb0 = ex2_(sb0), pb1 = ex2_(sb1);
        la2 = add2_(la2, pk2(pa0, pa1));
        lb2 = add2_(lb2, pk2(pb0, pb1));

        unsigned va = vsb + jp * 128;
        // key 0
        {
            u64 v0, v1, v2, v3, v4, v5, v6, v7;
            LDSV2(v0, v1, va, 0);
            LDSV2(v2, v3, va, 16);
            LDSV2(v4, v5, va, 32);
            LDSV2(v6, v7, va, 48);
            u64 pA = pk2(pa0, pa0), pB = pk2(pb0, pb0);
            oa[0] = fma2_(pA, v0, oa[0]);  ob[0] = fma2_(pB, v0, ob[0]);
            oa[1] = fma2_(pA, v1, oa[1]);  ob[1] = fma2_(pB, v1, ob[1]);
            oa[2] = fma2_(pA, v2, oa[2]);  ob[2] = fma2_(pB, v2, ob[2]);
            oa[3] = fma2_(pA, v3, oa[3]);  ob[3] = fma2_(pB, v3, ob[3]);
            oa[4] = fma2_(pA, v4, oa[4]);  ob[4] = fma2_(pB, v4, ob[4]);
            oa[5] = fma2_(pA, v5, oa[5]);  ob[5] = fma2_(pB, v5, ob[5]);
            oa[6] = fma2_(pA, v6, oa[6]);  ob[6] = fma2_(pB, v6, ob[6]);
            oa[7] = fma2_(pA, v7, oa[7]);  ob[7] = fma2_(pB, v7, ob[7]);
        }
        // key 1
        {
            u64 v0, v1, v2, v3, v4, v5, v6, v7;
            LDSV2(v0, v1, va, 64);
            LDSV2(v2, v3, va, 80);
            LDSV2(v4, v5, va, 96);
            LDSV2(v6, v7, va, 112);
            u64 pA = pk2(pa1, pa1), pB = pk2(pb1, pb1);
            oa[0] = fma2_(pA, v0, oa[0]);  ob[0] = fma2_(pB, v0, ob[0]);
            oa[1] = fma2_(pA, v1, oa[1]);  ob[1] = fma2_(pB, v1, ob[1]);
            oa[2] = fma2_(pA, v2, oa[2]);  ob[2] = fma2_(pB, v2, ob[2]);
            oa[3] = fma2_(pA, v3, oa[3]);  ob[3] = fma2_(pB, v3, ob[3]);
            oa[4] = fma2_(pA, v4, oa[4]);  ob[4] = fma2_(pB, v4, ob[4]);
            oa[5] = fma2_(pA, v5, oa[5]);  ob[5] = fma2_(pB, v5, ob[5]);
            oa[6] = fma2_(pA, v6, oa[6]);  ob[6] = fma2_(pB, v6, ob[6]);
            oa[7] = fma2_(pA, v7, oa[7]);  ob[7] = fma2_(pB, v7, ob[7]);
        }
    }

    // write split partials (unnormalized; shared fixed offset -> no m needed)
#pragma unroll 2
    for (int r = 0; r < 2; r++) {
        int row = (r == 0) ? rowA : rowB;
        u64 lp = (r == 0) ? la2 : lb2;
        const u64* o2 = (r == 0) ? oa : ob;
        float l0, l1;
        upk2(lp, l0, l1);
        size_t pidx = ((size_t)bh * S_ + row) * SPLITS + split;
        g_pl[pidx] = l0 + l1;
        float o[16];
#pragma unroll
        for (int i = 0; i < 8; i++) upk2(o2[i], o[2 * i], o[2 * i + 1]);
        float4* po = (float4*)&g_po[pidx * D_];
#pragma unroll
        for (int i = 0; i < 4; i++)
            po[i] = make_float4(o[4 * i], o[4 * i + 1], o[4 * i + 2], o[4 * i + 3]);
    }
}

// ============================================================================
// Combine split-K partials -> out[B, Q, H, D]  (shared offset: plain sums)
// ============================================================================
__global__ __launch_bounds__(256) void combine_kernel(float* __restrict__ out)
{
    int g  = blockIdx.x * 256 + threadIdx.x;   // 0 .. BH_*S_-1
    int bh = g >> 11;
    int sq = g & 2047;
    int b  = bh >> 3, h = bh & 7;

    size_t base = (size_t)g * SPLITS;
    float L = 0.f;
    float o[16];
#pragma unroll
    for (int i = 0; i < 16; i++) o[i] = 0.f;

#pragma unroll
    for (int s = 0; s < SPLITS; s++) {
        L += g_pl[base + s];
        const float4* po = (const float4*)&g_po[(base + s) * D_];
#pragma unroll
        for (int i = 0; i < 4; i++) {
            float4 t = po[i];
            o[4 * i + 0] += t.x;
            o[4 * i + 1] += t.y;
            o[4 * i + 2] += t.z;
            o[4 * i + 3] += t.w;
        }
    }

    float inv = 1.0f / L;
    float* op = out + (((size_t)b * S_ + sq) * H_ + h) * D_;
#pragma unroll
    for (int i = 0; i < 4; i++)
        ((float4*)op)[i] = make_float4(o[4 * i] * inv, o[4 * i + 1] * inv,
                                       o[4 * i + 2] * inv, o[4 * i + 3] * inv);
}

// ============================================================================
extern "C" void kernel_launch(void* const* d_in, const int* in_sizes, int n_in,
                              void* d_out, int out_size)
{
    const float* q_x  = (const float*)d_in[0];
    const float* kv_x = (const float*)d_in[1];
    const float* w_q  = (const float*)d_in[2];
    const float* w_k  = (const float*)d_in[3];
    const float* w_v  = (const float*)d_in[4];
    float* out = (float*)d_out;

    const int proj_smem = (C_ * WS + C_ * XS) * sizeof(float);  // ~100 KB
    cudaFuncSetAttribute(proj_kernel,
                         cudaFuncAttributeMaxDynamicSharedMemorySize, proj_smem);
    const int attn_smem = 2 * JSPLIT * D_ * sizeof(float);      // 32 KB
    cudaFuncSetAttribute(attn_kernel,
                         cudaFuncAttributeMaxDynamicSharedMemorySize, attn_smem);

    proj_kernel<<<dim3(B_ * S_ / PR, 3), 256, proj_smem>>>(q_x, kv_x, w_q, w_k, w_v);
    attn_kernel<<<dim3((S_ / QT2) * SPLITS, H_, B_), 128, attn_smem>>>();
    combine_kernel<<<(BH_ * S_) / 256, 256>>>(out);
}

// round 16
// speedup vs baseline: 1.0676x; 1.0676x over previous
#include <cuda_runtime.h>
#include <math.h>

typedef unsigned long long u64;

#define B_ 4
#define S_ 2048
#define C_ 128
#define H_ 8
#define D_ 16
#define BH_ (B_*H_)
#define SPLITS 4
#define JSPLIT (S_/SPLITS)   // 512 keys per split (staged whole, 64 KB)
#define QT2 256              // q rows per attn CTA (2 per thread)

#define LOG2E 1.4426950408889634f
#define EXP_OFF2 5.7707801636f   // 4.0 * log2(e), applied in log2 domain

// Scratch (device globals: no allocs allowed).
__device__ float g_q[(size_t)BH_*S_*D_];
// g_k stored PAIR-TRANSPOSED: g_k[bh][jp][d][par] = k[bh][2*jp+par][d]
__device__ float g_k[(size_t)BH_*S_*D_];
__device__ float g_v[(size_t)BH_*S_*D_];
// split-K partials: per (bh, row, split): l, o[16] (unnormalized, shared offset)
__device__ float g_pl[(size_t)BH_*S_*SPLITS];
__device__ float g_po[(size_t)BH_*S_*SPLITS*D_];

// ---- packed f32x2 helpers (FFMA2: PTX-only, 2x fp32 FMA throughput) ----
__device__ __forceinline__ u64 pk2(float lo, float hi) {
    u64 r; asm("mov.b64 %0,{%1,%2};" : "=l"(r) : "f"(lo), "f"(hi)); return r;
}
__device__ __forceinline__ void upk2(u64 v, float& lo, float& hi) {
    asm("mov.b64 {%0,%1},%2;" : "=f"(lo), "=f"(hi) : "l"(v));
}
__device__ __forceinline__ u64 fma2_(u64 a, u64 b, u64 c) {
    u64 d; asm("fma.rn.f32x2 %0,%1,%2,%3;" : "=l"(d) : "l"(a), "l"(b), "l"(c)); return d;
}
__device__ __forceinline__ u64 mul2_(u64 a, u64 b) {
    u64 d; asm("mul.rn.f32x2 %0,%1,%2;" : "=l"(d) : "l"(a), "l"(b)); return d;
}
__device__ __forceinline__ u64 add2_(u64 a, u64 b) {
    u64 d; asm("add.rn.f32x2 %0,%1,%2;" : "=l"(d) : "l"(a), "l"(b)); return d;
}
__device__ __forceinline__ float ex2_(float x) {
    float y; asm("ex2.approx.f32 %0,%1;" : "=f"(y) : "f"(x)); return y;
}
// 16-byte shared load -> two u64 pairs (LDS.128), immediate offset folded in.
#define LDSV2(a, b, addr, OFF) \
    asm volatile("ld.shared.v2.b64 {%0,%1},[%2+" #OFF "];" \
                 : "=l"(a), "=l"(b) : "r"(addr))

// ============================================================================
// Projection: out[b,h,s,d] = sum_c x[b,s,c] * w[h*16+d, c]  (q scaled 1/4)
// 256 threads, 8 rows x 4 cols per thread (high ILP, measured 33.5us).
// K output written pair-transposed (free: same 2x STG.128, interleaved).
// ============================================================================
#define PR 64     // x rows per CTA
#define WS 132    // padded stride for w_s
#define XS 68     // padded stride for x_sT

__global__ __launch_bounds__(256) void proj_kernel(
    const float* __restrict__ q_x, const float* __restrict__ kv_x,
    const float* __restrict__ w_q, const float* __restrict__ w_k,
    const float* __restrict__ w_v)
{
    extern __shared__ float sm[];
    float* w_s = sm;               // w_s[c*WS + o]
    float* x_s = sm + C_ * WS;     // x_s[c*XS + r]

    int proj = blockIdx.y;
    const float* x  = (proj == 0) ? q_x : kv_x;
    const float* w  = (proj == 0) ? w_q : (proj == 1 ? w_k : w_v);
    float*       og = (proj == 0) ? g_q : (proj == 1 ? g_k : g_v);
    float scale = (proj == 0) ? 0.25f : 1.0f;   // 1/sqrt(16)
    bool kmode = (proj == 1);

    int tid  = threadIdx.x;
    int row0 = blockIdx.x * PR;

    for (int i = tid; i < C_ * C_; i += 256) {
        int o = i >> 7, c = i & 127;
        w_s[c * WS + o] = w[i];
    }
    {
        const float* xg = x + (size_t)row0 * C_;
        for (int i = tid; i < PR * C_; i += 256) {
            int r = i >> 7, c = i & 127;
            x_s[c * XS + r] = xg[i];
        }
    }
    __syncthreads();

    int rg = tid >> 5, cg = tid & 31;
    int r0 = rg * 8, c0 = cg * 4;

    unsigned wb = (unsigned)__cvta_generic_to_shared(w_s) + c0 * 4;
    unsigned xb = (unsigned)__cvta_generic_to_shared(x_s) + r0 * 4;

    u64 acc[4][4];
#pragma unroll
    for (int m = 0; m < 4; m++)
#pragma unroll
        for (int j = 0; j < 4; j++) acc[m][j] = 0ull;

#pragma unroll 8
    for (int k = 0; k < C_; k++) {
        u64 b01, b23;
        LDSV2(b01, b23, wb + k * (WS * 4), 0);
        u64 x01, x23, x45, x67;
        unsigned xa = xb + k * (XS * 4);
        LDSV2(x01, x23, xa, 0);
        LDSV2(x45, x67, xa, 16);

        float b0, b1, b2, b3;
        upk2(b01, b0, b1); upk2(b23, b2, b3);
        u64 bd0 = pk2(b0, b0), bd1 = pk2(b1, b1);
        u64 bd2 = pk2(b2, b2), bd3 = pk2(b3, b3);

        acc[0][0] = fma2_(x01, bd0, acc[0][0]);
        acc[0][1] = fma2_(x01, bd1, acc[0][1]);
        acc[0][2] = fma2_(x01, bd2, acc[0][2]);
        acc[0][3] = fma2_(x01, bd3, acc[0][3]);
        acc[1][0] = fma2_(x23, bd0, acc[1][0]);
        acc[1][1] = fma2_(x23, bd1, acc[1][1]);
        acc[1][2] = fma2_(x23, bd2, acc[1][2]);
        acc[1][3] = fma2_(x23, bd3, acc[1][3]);
        acc[2][0] = fma2_(x45, bd0, acc[2][0]);
        acc[2][1] = fma2_(x45, bd1, acc[2][1]);
        acc[2][2] = fma2_(x45, bd2, acc[2][2]);
        acc[2][3] = fma2_(x45, bd3, acc[2][3]);
        acc[3][0] = fma2_(x67, bd0, acc[3][0]);
        acc[3][1] = fma2_(x67, bd1, acc[3][1]);
        acc[3][2] = fma2_(x67, bd2, acc[3][2]);
        acc[3][3] = fma2_(x67, bd3, acc[3][3]);
    }

    int h  = c0 >> 4;
    int d0 = c0 & 15;
#pragma unroll
    for (int m = 0; m < 4; m++) {
        float lo[4], hi[4];   // lo = even row (gr), hi = odd row (gr+1)
#pragma unroll
        for (int j = 0; j < 4; j++) upk2(acc[m][j], lo[j], hi[j]);
        int gr = row0 + r0 + 2 * m;
        int b  = gr >> 11;
        int s  = gr & 2047;
        if (!kmode) {
            float* base = &og[((size_t)(b * H_ + h) * S_ + s) * D_ + d0];
            *(float4*)base = make_float4(lo[0] * scale, lo[1] * scale,
                                         lo[2] * scale, lo[3] * scale);
            *(float4*)(base + D_) = make_float4(hi[0] * scale, hi[1] * scale,
                                                hi[2] * scale, hi[3] * scale);
        } else {
            // pair-transposed: g_k[bh][jp=s/2][d][par], 8 contiguous floats
            float* base = &og[(size_t)(b * H_ + h) * S_ * D_
                              + (size_t)(s >> 1) * 32 + d0 * 2];
            *(float4*)base       = make_float4(lo[0], hi[0], lo[1], hi[1]);
            *(float4*)(base + 4) = make_float4(lo[2], hi[2], lo[3], hi[3]);
        }
    }
}

// ============================================================================
// Attention (R9 best-measured config: split-K x4, 2 q-rows/thread, key-pair
// packed scores, whole 512-key split staged in 64 KB, launch_bounds(128,3)).
// K arrives already pair-transposed -> staging is a pure float4 copy.
// ============================================================================
__global__ __launch_bounds__(128, 3) void attn_kernel()
{
    extern __shared__ float smv[];
    float*  kt  = smv;                           // 32 KB (transposed key pairs)
    float4* v_s = (float4*)(smv + JSPLIT * D_);  // 32 KB

    int split = blockIdx.x & (SPLITS - 1);
    int qb    = blockIdx.x >> 2;
    int b = blockIdx.z, h = blockIdx.y;
    int bh = b * H_ + h;
    int rowA = qb * QT2 + threadIdx.x;
    int rowB = rowA + 128;

    // q rows as BROADCAST pairs, pre-scaled by log2(e)
    u64 qa2[16], qb2[16];
    {
        const float* ga = g_q + ((size_t)bh * S_ + rowA) * D_;
        const float* gb = g_q + ((size_t)bh * S_ + rowB) * D_;
#pragma unroll
        for (int i = 0; i < 4; i++) {
            float4 t = ((const float4*)ga)[i];
            float4 u = ((const float4*)gb)[i];
            qa2[4*i+0] = pk2(t.x * LOG2E, t.x * LOG2E);
            qa2[4*i+1] = pk2(t.y * LOG2E, t.y * LOG2E);
            qa2[4*i+2] = pk2(t.z * LOG2E, t.z * LOG2E);
            qa2[4*i+3] = pk2(t.w * LOG2E, t.w * LOG2E);
            qb2[4*i+0] = pk2(u.x * LOG2E, u.x * LOG2E);
            qb2[4*i+1] = pk2(u.y * LOG2E, u.y * LOG2E);
            qb2[4*i+2] = pk2(u.z * LOG2E, u.z * LOG2E);
            qb2[4*i+3] = pk2(u.w * LOG2E, u.w * LOG2E);
        }
    }

    u64 oa[8], ob[8];
#pragma unroll
    for (int i = 0; i < 8; i++) { oa[i] = 0ull; ob[i] = 0ull; }
    u64 la2 = 0ull, lb2 = 0ull;   // packed (key0, key1) row-sum accumulators

    int j0 = split * JSPLIT;
    // stage K (already transposed) + V: pure float4 copies
    {
        const float4* kg = (const float4*)(g_k + (size_t)bh * S_ * D_ + (size_t)j0 * D_);
        const float4* vg = (const float4*)(g_v + ((size_t)bh * S_ + j0) * D_);
        float4* kts = (float4*)kt;
        for (int i = threadIdx.x; i < JSPLIT * 4; i += 128) {
            kts[i] = kg[i];
            v_s[i] = vg[i];
        }
    }
    __syncthreads();

    unsigned ksb = (unsigned)__cvta_generic_to_shared(kt);
    unsigned vsb = (unsigned)__cvta_generic_to_shared(v_s);
    u64 noff2 = pk2(-EXP_OFF2, -EXP_OFF2);

#pragma unroll 2
    for (int jp = 0; jp < JSPLIT / 2; jp++) {
        unsigned ka = ksb + jp * 128;
        u64 t0,t1,t2,t3,t4,t5,t6,t7,t8,t9,t10,t11,t12,t13,t14,t15;
        LDSV2(t0, t1, ka, 0);
        LDSV2(t2, t3, ka, 16);
        LDSV2(t4, t5, ka, 32);
        LDSV2(t6, t7, ka, 48);
        LDSV2(t8, t9, ka, 64);
        LDSV2(t10, t11, ka, 80);
        LDSV2(t12, t13, ka, 96);
        LDSV2(t14, t15, ka, 112);

        // row A: two partial chains, offset folded into seed
        u64 sA0 = fma2_(qa2[0], t0, noff2);
        u64 sA1 = mul2_(qa2[8], t8);
        sA0 = fma2_(qa2[1], t1, sA0);   sA1 = fma2_(qa2[9],  t9,  sA1);
        sA0 = fma2_(qa2[2], t2, sA0);   sA1 = fma2_(qa2[10], t10, sA1);
        sA0 = fma2_(qa2[3], t3, sA0);   sA1 = fma2_(qa2[11], t11, sA1);
        sA0 = fma2_(qa2[4], t4, sA0);   sA1 = fma2_(qa2[12], t12, sA1);
        sA0 = fma2_(qa2[5], t5, sA0);   sA1 = fma2_(qa2[13], t13, sA1);
        sA0 = fma2_(qa2[6], t6, sA0);   sA1 = fma2_(qa2[14], t14, sA1);
        sA0 = fma2_(qa2[7], t7, sA0);   sA1 = fma2_(qa2[15], t15, sA1);
        sA0 = add2_(sA0, sA1);

        // row B
        u64 sB0 = fma2_(qb2[0], t0, noff2);
        u64 sB1 = mul2_(qb2[8], t8);
        sB0 = fma2_(qb2[1], t1, sB0);   sB1 = fma2_(qb2[9],  t9,  sB1);
        sB0 = fma2_(qb2[2], t2, sB0);   sB1 = fma2_(qb2[10], t10, sB1);
        sB0 = fma2_(qb2[3], t3, sB0);   sB1 = fma2_(qb2[11], t11, sB1);
        sB0 = fma2_(qb2[4], t4, sB0);   sB1 = fma2_(qb2[12], t12, sB1);
        sB0 = fma2_(qb2[5], t5, sB0);   sB1 = fma2_(qb2[13], t13, sB1);
        sB0 = fma2_(qb2[6], t6, sB0);   sB1 = fma2_(qb2[14], t14, sB1);
        sB0 = fma2_(qb2[7], t7, sB0);   sB1 = fma2_(qb2[15], t15, sB1);
        sB0 = add2_(sB0, sB1);

        float sa0, sa1, sb0, sb1;
        upk2(sA0, sa0, sa1);
        upk2(sB0, sb0, sb1);
        float pa0 = ex2_(sa0), pa1 = ex2_(sa1);
        float pb0 = ex2_(sb0), pb1 = ex2_(sb1);
        la2 = add2_(la2, pk2(pa0, pa1));
        lb2 = add2_(lb2, pk2(pb0, pb1));

        unsigned va = vsb + jp * 128;
        // key 0
        {
            u64 v0, v1, v2, v3, v4, v5, v6, v7;
            LDSV2(v0, v1, va, 0);
            LDSV2(v2, v3, va, 16);
            LDSV2(v4, v5, va, 32);
            LDSV2(v6, v7, va, 48);
            u64 pA = pk2(pa0, pa0), pB = pk2(pb0, pb0);
            oa[0] = fma2_(pA, v0, oa[0]);  ob[0] = fma2_(pB, v0, ob[0]);
            oa[1] = fma2_(pA, v1, oa[1]);  ob[1] = fma2_(pB, v1, ob[1]);
            oa[2] = fma2_(pA, v2, oa[2]);  ob[2] = fma2_(pB, v2, ob[2]);
            oa[3] = fma2_(pA, v3, oa[3]);  ob[3] = fma2_(pB, v3, ob[3]);
            oa[4] = fma2_(pA, v4, oa[4]);  ob[4] = fma2_(pB, v4, ob[4]);
            oa[5] = fma2_(pA, v5, oa[5]);  ob[5] = fma2_(pB, v5, ob[5]);
            oa[6] = fma2_(pA, v6, oa[6]);  ob[6] = fma2_(pB, v6, ob[6]);
            oa[7] = fma2_(pA, v7, oa[7]);  ob[7] = fma2_(pB, v7, ob[7]);
        }
        // key 1
        {
            u64 v0, v1, v2, v3, v4, v5, v6, v7;
            LDSV2(v0, v1, va, 64);
            LDSV2(v2, v3, va, 80);
            LDSV2(v4, v5, va, 96);
            LDSV2(v6, v7, va, 112);
            u64 pA = pk2(pa1, pa1), pB = pk2(pb1, pb1);
            oa[0] = fma2_(pA, v0, oa[0]);  ob[0] = fma2_(pB, v0, ob[0]);
            oa[1] = fma2_(pA, v1, oa[1]);  ob[1] = fma2_(pB, v1, ob[1]);
            oa[2] = fma2_(pA, v2, oa[2]);  ob[2] = fma2_(pB, v2, ob[2]);
            oa[3] = fma2_(pA, v3, oa[3]);  ob[3] = fma2_(pB, v3, ob[3]);
            oa[4] = fma2_(pA, v4, oa[4]);  ob[4] = fma2_(pB, v4, ob[4]);
            oa[5] = fma2_(pA, v5, oa[5]);  ob[5] = fma2_(pB, v5, ob[5]);
            oa[6] = fma2_(pA, v6, oa[6]);  ob[6] = fma2_(pB, v6, ob[6]);
            oa[7] = fma2_(pA, v7, oa[7]);  ob[7] = fma2_(pB, v7, ob[7]);
        }
    }

    // write split partials (unnormalized; shared fixed offset -> no m needed)
#pragma unroll 2
    for (int r = 0; r < 2; r++) {
        int row = (r == 0) ? rowA : rowB;
        u64 lp = (r == 0) ? la2 : lb2;
        const u64* o2 = (r == 0) ? oa : ob;
        float l0, l1;
        upk2(lp, l0, l1);
        size_t pidx = ((size_t)bh * S_ + row) * SPLITS + split;
        g_pl[pidx] = l0 + l1;
        float o[16];
#pragma unroll
        for (int i = 0; i < 8; i++) upk2(o2[i], o[2 * i], o[2 * i + 1]);
        float4* po = (float4*)&g_po[pidx * D_];
#pragma unroll
        for (int i = 0; i < 4; i++)
            po[i] = make_float4(o[4 * i], o[4 * i + 1], o[4 * i + 2], o[4 * i + 3]);
    }
}

// ============================================================================
// Combine split-K partials -> out[B, Q, H, D]  (shared offset: plain sums)
// ============================================================================
__global__ __launch_bounds__(256) void combine_kernel(float* __restrict__ out)
{
    int g  = blockIdx.x * 256 + threadIdx.x;   // 0 .. BH_*S_-1
    int bh = g >> 11;
    int sq = g & 2047;
    int b  = bh >> 3, h = bh & 7;

    size_t base = (size_t)g * SPLITS;
    float L = 0.f;
    float o[16];
#pragma unroll
    for (int i = 0; i < 16; i++) o[i] = 0.f;

#pragma unroll
    for (int s = 0; s < SPLITS; s++) {
        L += g_pl[base + s];
        const float4* po = (const float4*)&g_po[(base + s) * D_];
#pragma unroll
        for (int i = 0; i < 4; i++) {
            float4 t = po[i];
            o[4 * i + 0] += t.x;
            o[4 * i + 1] += t.y;
            o[4 * i + 2] += t.z;
            o[4 * i + 3] += t.w;
        }
    }

    float inv = 1.0f / L;
    float* op = out + (((size_t)b * S_ + sq) * H_ + h) * D_;
#pragma unroll
    for (int i = 0; i < 4; i++)
        ((float4*)op)[i] = make_float4(o[4 * i] * inv, o[4 * i + 1] * inv,
                                       o[4 * i + 2] * inv, o[4 * i + 3] * inv);
}

// ============================================================================
extern "C" void kernel_launch(void* const* d_in, const int* in_sizes, int n_in,
                              void* d_out, int out_size)
{
    const float* q_x  = (const float*)d_in[0];
    const float* kv_x = (const float*)d_in[1];
    const float* w_q  = (const float*)d_in[2];
    const float* w_k  = (const float*)d_in[3];
    const float* w_v  = (const float*)d_in[4];
    float* out = (float*)d_out;

    const int proj_smem = (C_ * WS + C_ * XS) * sizeof(float);  // ~100 KB
    cudaFuncSetAttribute(proj_kernel,
                         cudaFuncAttributeMaxDynamicSharedMemorySize, proj_smem);
    const int attn_smem = 2 * JSPLIT * D_ * sizeof(float);      // 64 KB
    cudaFuncSetAttribute(attn_kernel,
                         cudaFuncAttributeMaxDynamicSharedMemorySize, attn_smem);

    proj_kernel<<<dim3(B_ * S_ / PR, 3), 256, proj_smem>>>(q_x, kv_x, w_q, w_k, w_v);
    attn_kernel<<<dim3((S_ / QT2) * SPLITS, H_, B_), 128, attn_smem>>>();
    combine_kernel<<<(BH_ * S_) / 256, 256>>>(out);
}